// round 4
// baseline (speedup 1.0000x reference)
#include <cuda_runtime.h>
#include <cuda_bf16.h>
#include <cstdint>

// Problem constants
#define Bsz 4
#define Sq  2048
#define Hd  1024
#define NH  16
#define HD  64
#define BH  (Bsz*NH)          // 64
#define M1  (Bsz*Sq)          // 8192
#define QKV_STRIDE ((size_t)BH*Sq*HD) // 8388608 elems per Q/K/V

// Scratch (__device__ globals; g_qkv holds tf32 bit patterns)
__device__ uint32_t g_qkv[3ull * QKV_STRIDE];   // Q(pre-scaled),K,V each [BH,S,HD]
__device__ float    g_ctx[(size_t)M1 * Hd];     // [B, S, H]

// ---------------------------------------------------------------------------
// Helpers
// ---------------------------------------------------------------------------
__device__ __forceinline__ uint32_t f2tf32(float f) {
    uint32_t u;
    asm("cvt.rna.tf32.f32 %0, %1;" : "=r"(u) : "f"(f));
    return u;
}
__device__ __forceinline__ void cp_async16(void* smem_dst, const void* gmem_src) {
    uint32_t s = (uint32_t)__cvta_generic_to_shared(smem_dst);
    asm volatile("cp.async.ca.shared.global [%0], [%1], 16;\n" :: "r"(s), "l"(gmem_src));
}
#define CP_COMMIT() asm volatile("cp.async.commit_group;\n")
#define CP_WAIT(n)  asm volatile("cp.async.wait_group %0;\n" :: "n"(n))

#define MMA_TF32(acc, a, b0, b1)                                               \
    asm volatile(                                                              \
        "mma.sync.aligned.m16n8k8.row.col.f32.tf32.tf32.f32 "                  \
        "{%0,%1,%2,%3}, {%4,%5,%6,%7}, {%8,%9}, {%0,%1,%2,%3};\n"              \
        : "+f"((acc)[0]), "+f"((acc)[1]), "+f"((acc)[2]), "+f"((acc)[3])       \
        : "r"((a)[0]), "r"((a)[1]), "r"((a)[2]), "r"((a)[3]),                  \
          "r"(b0), "r"(b1))

// ---------------------------------------------------------------------------
// TF32 tensor-core GEMM: C = A[M,K] @ B[K,N] + bias. 128x128x16 tiles,
// 256 thr, warp tile 64x32. cvt at STS time -> inner loop pure LDS+MMA.
// MODE 0: fp32 row-major C. MODE 1: tf32-bits scatter into g_qkv (Q *= 1/8).
// ---------------------------------------------------------------------------
#define BKP 20
#define BNP 136

template<int MODE>
__global__ __launch_bounds__(256)
void tf32_gemm(const float* __restrict__ A, const float* __restrict__ Bm,
               const float* __restrict__ bias, float* __restrict__ C,
               int M, int N, int K)
{
    __shared__ uint32_t As[2][128 * BKP];
    __shared__ uint32_t Bs[2][16 * BNP];

    const int tid  = threadIdx.x;
    const int lane = tid & 31;
    const int warp = tid >> 5;
    const int wm   = (warp >> 2) * 64;
    const int wn   = (warp & 3) * 32;
    const int brow = blockIdx.y * 128;
    const int bcol = blockIdx.x * 128;
    const int lg = lane >> 2;
    const int lt = lane & 3;

    // loader indices (2 chunks of A, 2 of B per thread)
    const int arow0 = tid >> 2,        aseg0 = (tid & 3) * 4;
    const int arow1 = (tid + 256) >> 2, aseg1 = aseg0;
    const int brw0  = tid >> 5,        bseg0 = (tid & 31) * 4;
    const int brw1  = (tid + 256) >> 5, bseg1 = bseg0;

    float4 ar0, ar1, br0, br1;
    auto ldg_tile = [&](int k0) {
        ar0 = *(const float4*)(A + (size_t)(brow + arow0) * K + k0 + aseg0);
        ar1 = *(const float4*)(A + (size_t)(brow + arow1) * K + k0 + aseg1);
        br0 = *(const float4*)(Bm + (size_t)(k0 + brw0) * N + bcol + bseg0);
        br1 = *(const float4*)(Bm + (size_t)(k0 + brw1) * N + bcol + bseg1);
    };
    auto sts_tile = [&](int buf) {
        uint4 u;
        u.x = f2tf32(ar0.x); u.y = f2tf32(ar0.y); u.z = f2tf32(ar0.z); u.w = f2tf32(ar0.w);
        *(uint4*)&As[buf][arow0 * BKP + aseg0] = u;
        u.x = f2tf32(ar1.x); u.y = f2tf32(ar1.y); u.z = f2tf32(ar1.z); u.w = f2tf32(ar1.w);
        *(uint4*)&As[buf][arow1 * BKP + aseg1] = u;
        u.x = f2tf32(br0.x); u.y = f2tf32(br0.y); u.z = f2tf32(br0.z); u.w = f2tf32(br0.w);
        *(uint4*)&Bs[buf][brw0 * BNP + bseg0] = u;
        u.x = f2tf32(br1.x); u.y = f2tf32(br1.y); u.z = f2tf32(br1.z); u.w = f2tf32(br1.w);
        *(uint4*)&Bs[buf][brw1 * BNP + bseg1] = u;
    };

    float acc[4][4][4];
#pragma unroll
    for (int mi = 0; mi < 4; mi++)
#pragma unroll
        for (int ni = 0; ni < 4; ni++)
#pragma unroll
            for (int r = 0; r < 4; r++) acc[mi][ni][r] = 0.f;

    ldg_tile(0);
    sts_tile(0);
    __syncthreads();

    const int NIT = K / 16;
    int buf = 0;
    for (int it = 0; it < NIT; ++it) {
        if (it + 1 < NIT) ldg_tile((it + 1) * 16);   // overlap with compute

#pragma unroll
        for (int ks = 0; ks < 2; ++ks) {
            const int k8 = ks * 8;
            uint32_t af[4][4], bf[4][2];
#pragma unroll
            for (int mi = 0; mi < 4; mi++) {
                int row = wm + mi * 16 + lg;
                af[mi][0] = As[buf][row * BKP + k8 + lt];
                af[mi][1] = As[buf][(row + 8) * BKP + k8 + lt];
                af[mi][2] = As[buf][row * BKP + k8 + lt + 4];
                af[mi][3] = As[buf][(row + 8) * BKP + k8 + lt + 4];
            }
#pragma unroll
            for (int ni = 0; ni < 4; ni++) {
                int col = wn + ni * 8 + lg;
                bf[ni][0] = Bs[buf][(k8 + lt) * BNP + col];
                bf[ni][1] = Bs[buf][(k8 + 4 + lt) * BNP + col];
            }
#pragma unroll
            for (int mi = 0; mi < 4; mi++)
#pragma unroll
                for (int ni = 0; ni < 4; ni++)
                    MMA_TF32(acc[mi][ni], af[mi], bf[ni][0], bf[ni][1]);
        }
        __syncthreads();
        if (it + 1 < NIT) {
            sts_tile(buf ^ 1);
            __syncthreads();
        }
        buf ^= 1;
    }

    // epilogue
#pragma unroll
    for (int mi = 0; mi < 4; mi++) {
#pragma unroll
        for (int ni = 0; ni < 4; ni++) {
            int gr = brow + wm + mi * 16 + lg;
            int gc = bcol + wn + ni * 8 + lt * 2;
            float bx = bias[gc], by = bias[gc + 1];
            float2 v0 = make_float2(acc[mi][ni][0] + bx, acc[mi][ni][1] + by);
            float2 v1 = make_float2(acc[mi][ni][2] + bx, acc[mi][ni][3] + by);
            if (MODE == 0) {
                *(float2*)&C[(size_t)gr * N + gc]       = v0;
                *(float2*)&C[(size_t)(gr + 8) * N + gc] = v1;
            } else {
                int which = gc >> 10;
                int hh    = (gc >> 6) & 15;
                int d     = gc & 63;
                float scale = (which == 0) ? 0.125f : 1.0f;  // fold 1/sqrt(HD) into Q
#pragma unroll
                for (int rr = 0; rr < 2; rr++) {
                    int row = gr + rr * 8;
                    int b   = row >> 11;
                    int s   = row & 2047;
                    float2 v = rr ? v1 : v0;
                    uint2 u;
                    u.x = f2tf32(v.x * scale);
                    u.y = f2tf32(v.y * scale);
                    size_t idx = (size_t)which * QKV_STRIDE
                               + (((size_t)(b * NH + hh) * Sq + s) * HD) + d;
                    *(uint2*)&g_qkv[idx] = u;
                }
            }
        }
    }
}

// ---------------------------------------------------------------------------
// TF32 tensor-core causal flash attention.
// BM=128 (8 warps x 16 rows), BN=64, HD=64. Q frags in regs, K/V cp.async
// double-buffered, m/l in regs, P via warp-private smem region.
// Smem pad 72 (72%32==8): all fragment access patterns conflict-free.
// ---------------------------------------------------------------------------
#define AT_PAD 72
#define AT_KV_SZ (64 * AT_PAD)                       // 4608 words per K or V buf
#define AT_SMEM_WORDS (4 * AT_KV_SZ + 128 * AT_PAD)  // 27648 words = 110592 B

__global__ __launch_bounds__(256)
void attn_tc(const uint32_t* __restrict__ gQ, const uint32_t* __restrict__ gK,
             const uint32_t* __restrict__ gV)
{
    extern __shared__ uint32_t sm[];
    uint32_t* KsBuf[2] = { sm,             sm + 2 * AT_KV_SZ };
    uint32_t* VsBuf[2] = { sm + AT_KV_SZ,  sm + 3 * AT_KV_SZ };
    uint32_t* Ps       = sm + 4 * AT_KV_SZ;          // [128][AT_PAD]

    const int tid  = threadIdx.x;
    const int lane = tid & 31;
    const int warp = tid >> 5;
    const int lg = lane >> 2;
    const int lt = lane & 3;
    const int qt = 15 - blockIdx.x;     // heavy tiles first
    const int bh = blockIdx.y;
    const int q0 = qt * 128;
    const int wm = warp * 16;

    const uint32_t* q_ptr = gQ + ((size_t)bh * Sq + q0) * HD;

    // prefetch Q (128x64) into Ps
#pragma unroll
    for (int r = 0; r < 8; r++) {
        int f = tid + r * 256;
        int row = f >> 4, seg = f & 15;
        cp_async16(&Ps[row * AT_PAD + seg * 4], q_ptr + (size_t)row * HD + seg * 4);
    }
    CP_COMMIT();

    auto load_kv = [&](int kt, int b) {
        const uint32_t* k_ptr = gK + ((size_t)bh * Sq + kt * 64) * HD;
        const uint32_t* v_ptr = gV + ((size_t)bh * Sq + kt * 64) * HD;
#pragma unroll
        for (int r = 0; r < 4; r++) {
            int f = tid + r * 256;
            int row = f >> 4, seg = f & 15;
            cp_async16(&KsBuf[b][row * AT_PAD + seg * 4], k_ptr + (size_t)row * HD + seg * 4);
            cp_async16(&VsBuf[b][row * AT_PAD + seg * 4], v_ptr + (size_t)row * HD + seg * 4);
        }
    };
    load_kv(0, 0);
    CP_COMMIT();

    CP_WAIT(1);           // Q landed
    __syncthreads();

    // Q fragments (warp-private rows of Ps; no further sync needed)
    uint32_t qf[8][4];
#pragma unroll
    for (int k = 0; k < 8; k++) {
        qf[k][0] = Ps[(wm + lg) * AT_PAD + k * 8 + lt];
        qf[k][1] = Ps[(wm + lg + 8) * AT_PAD + k * 8 + lt];
        qf[k][2] = Ps[(wm + lg) * AT_PAD + k * 8 + lt + 4];
        qf[k][3] = Ps[(wm + lg + 8) * AT_PAD + k * 8 + lt + 4];
    }

    float m_lo = -1e30f, m_hi = -1e30f, l_lo = 0.f, l_hi = 0.f;
    float o[8][4];
#pragma unroll
    for (int ni = 0; ni < 8; ni++)
#pragma unroll
        for (int c = 0; c < 4; c++) o[ni][c] = 0.f;

    const int row_lo = q0 + wm + lg;
    const int row_hi = row_lo + 8;
    const int nkt = 2 * qt + 2;

    for (int kt = 0; kt < nkt; kt++) {
        const int p = kt & 1;
        CP_WAIT(0);
        __syncthreads();                          // tile ready; prev tile reads done
        if (kt + 1 < nkt) { load_kv(kt + 1, p ^ 1); CP_COMMIT(); }

        const uint32_t* Ks = KsBuf[p];
        const uint32_t* Vs = VsBuf[p];

        // S = Q @ K^T  (scale pre-folded into Q)
        float s[8][4];
#pragma unroll
        for (int ni = 0; ni < 8; ni++)
#pragma unroll
            for (int c = 0; c < 4; c++) s[ni][c] = 0.f;

#pragma unroll
        for (int k = 0; k < 8; k++) {
#pragma unroll
            for (int ni = 0; ni < 8; ni++) {
                uint32_t b0 = Ks[(ni * 8 + lg) * AT_PAD + k * 8 + lt];
                uint32_t b1 = Ks[(ni * 8 + lg) * AT_PAD + k * 8 + lt + 4];
                MMA_TF32(s[ni], qf[k], b0, b1);
            }
        }

        // causal mask (only near the diagonal)
        if (kt >= 2 * qt) {
            const int colb = kt * 64;
#pragma unroll
            for (int ni = 0; ni < 8; ni++) {
                int c0 = colb + ni * 8 + lt * 2;
                if (c0 > row_lo)     s[ni][0] = -1e30f;
                if (c0 + 1 > row_lo) s[ni][1] = -1e30f;
                if (c0 > row_hi)     s[ni][2] = -1e30f;
                if (c0 + 1 > row_hi) s[ni][3] = -1e30f;
            }
        }

        // online softmax (row stats in regs, reduce over the 4-lane quad)
        float rx_lo = -1e30f, rx_hi = -1e30f;
#pragma unroll
        for (int ni = 0; ni < 8; ni++) {
            rx_lo = fmaxf(rx_lo, fmaxf(s[ni][0], s[ni][1]));
            rx_hi = fmaxf(rx_hi, fmaxf(s[ni][2], s[ni][3]));
        }
        rx_lo = fmaxf(rx_lo, __shfl_xor_sync(0xffffffffu, rx_lo, 1));
        rx_lo = fmaxf(rx_lo, __shfl_xor_sync(0xffffffffu, rx_lo, 2));
        rx_hi = fmaxf(rx_hi, __shfl_xor_sync(0xffffffffu, rx_hi, 1));
        rx_hi = fmaxf(rx_hi, __shfl_xor_sync(0xffffffffu, rx_hi, 2));

        float mn_lo = fmaxf(m_lo, rx_lo);
        float mn_hi = fmaxf(m_hi, rx_hi);
        float al_lo = __expf(m_lo - mn_lo);
        float al_hi = __expf(m_hi - mn_hi);
        m_lo = mn_lo; m_hi = mn_hi;

        float rs_lo = 0.f, rs_hi = 0.f;
#pragma unroll
        for (int ni = 0; ni < 8; ni++) {
            s[ni][0] = __expf(s[ni][0] - mn_lo);
            s[ni][1] = __expf(s[ni][1] - mn_lo);
            s[ni][2] = __expf(s[ni][2] - mn_hi);
            s[ni][3] = __expf(s[ni][3] - mn_hi);
            rs_lo += s[ni][0] + s[ni][1];
            rs_hi += s[ni][2] + s[ni][3];
        }
        rs_lo += __shfl_xor_sync(0xffffffffu, rs_lo, 1);
        rs_lo += __shfl_xor_sync(0xffffffffu, rs_lo, 2);
        rs_hi += __shfl_xor_sync(0xffffffffu, rs_hi, 1);
        rs_hi += __shfl_xor_sync(0xffffffffu, rs_hi, 2);
        l_lo = l_lo * al_lo + rs_lo;
        l_hi = l_hi * al_hi + rs_hi;

#pragma unroll
        for (int ni = 0; ni < 8; ni++) {
            o[ni][0] *= al_lo; o[ni][1] *= al_lo;
            o[ni][2] *= al_hi; o[ni][3] *= al_hi;
        }

        // store P (tf32) into warp-private Ps rows
#pragma unroll
        for (int ni = 0; ni < 8; ni++) {
            uint2 u0 = make_uint2(f2tf32(s[ni][0]), f2tf32(s[ni][1]));
            uint2 u1 = make_uint2(f2tf32(s[ni][2]), f2tf32(s[ni][3]));
            *(uint2*)&Ps[(wm + lg) * AT_PAD + ni * 8 + lt * 2]     = u0;
            *(uint2*)&Ps[(wm + lg + 8) * AT_PAD + ni * 8 + lt * 2] = u1;
        }
        __syncwarp();

        // O += P @ V
#pragma unroll
        for (int k = 0; k < 8; k++) {
            uint32_t pf[4];
            pf[0] = Ps[(wm + lg) * AT_PAD + k * 8 + lt];
            pf[1] = Ps[(wm + lg + 8) * AT_PAD + k * 8 + lt];
            pf[2] = Ps[(wm + lg) * AT_PAD + k * 8 + lt + 4];
            pf[3] = Ps[(wm + lg + 8) * AT_PAD + k * 8 + lt + 4];
#pragma unroll
            for (int ni = 0; ni < 8; ni++) {
                uint32_t b0 = Vs[(k * 8 + lt) * AT_PAD + ni * 8 + lg];
                uint32_t b1 = Vs[(k * 8 + lt + 4) * AT_PAD + ni * 8 + lg];
                MMA_TF32(o[ni], pf, b0, b1);
            }
        }
        __syncwarp();   // Ps reads done before next iteration's P store
    }

    // epilogue: normalize, write ctx [B,S,H]
    const int b = bh >> 4;
    const int h = bh & 15;
    const float inv_lo = 1.f / l_lo;
    const float inv_hi = 1.f / l_hi;
#pragma unroll
    for (int ni = 0; ni < 8; ni++) {
        int d = ni * 8 + lt * 2;
        float2 v0 = make_float2(o[ni][0] * inv_lo, o[ni][1] * inv_lo);
        float2 v1 = make_float2(o[ni][2] * inv_hi, o[ni][3] * inv_hi);
        size_t i0 = (((size_t)b * Sq + row_lo) << 10) + h * HD + d;
        size_t i1 = (((size_t)b * Sq + row_hi) << 10) + h * HD + d;
        *(float2*)&g_ctx[i0] = v0;
        *(float2*)&g_ctx[i1] = v1;
    }
}

// ---------------------------------------------------------------------------
// Launch
// ---------------------------------------------------------------------------
extern "C" void kernel_launch(void* const* d_in, const int* in_sizes, int n_in,
                              void* d_out, int out_size)
{
    const float* X       = (const float*)d_in[0];
    const float* W_qkv   = (const float*)d_in[2];
    const float* b_qkv   = (const float*)d_in[3];
    const float* W_dense = (const float*)d_in[4];
    const float* b_dense = (const float*)d_in[5];
    float* out = (float*)d_out;

    (void)in_sizes; (void)n_in; (void)out_size;

    cudaFuncSetAttribute(attn_tc,
                         cudaFuncAttributeMaxDynamicSharedMemorySize,
                         AT_SMEM_WORDS * 4);

    // 1. QKV projection -> tf32 bits in head layout (Q pre-scaled by 1/8)
    tf32_gemm<1><<<dim3(3 * Hd / 128, M1 / 128), 256>>>(
        X, W_qkv, b_qkv, nullptr, M1, 3 * Hd, Hd);

    // 2. tensor-core causal flash attention
    {
        uint32_t* base;
        cudaGetSymbolAddress((void**)&base, g_qkv);
        attn_tc<<<dim3(16, BH), 256, AT_SMEM_WORDS * 4>>>(
            base, base + QKV_STRIDE, base + 2 * QKV_STRIDE);
    }

    // 3. output projection
    {
        float* ctx;
        cudaGetSymbolAddress((void**)&ctx, g_ctx);
        tf32_gemm<0><<<dim3(Hd / 128, M1 / 128), 256>>>(
            ctx, W_dense, b_dense, out, M1, Hd, Hd);
    }
}